// round 15
// baseline (speedup 1.0000x reference)
#include <cuda_runtime.h>
#include <math.h>
#include <stdint.h>

// Problem constants
#define NB 128   // batch
#define TS 512   // timesteps
#define DI 512   // input dim
#define HD 512   // hidden dim

typedef unsigned long long ull;

// ---------------- packed f32x2 helpers (sm_100+ FFMA2 path) ----------------
__device__ __forceinline__ void fma2(ull& acc, ull a, ull b) {
    asm("fma.rn.f32x2 %0, %1, %2, %0;" : "+l"(acc) : "l"(a), "l"(b));
}
__device__ __forceinline__ void add2(ull& a, ull b) {
    asm("add.rn.f32x2 %0, %0, %1;" : "+l"(a) : "l"(b));
}
__device__ __forceinline__ void unpack2(ull v, float& lo, float& hi) {
    unsigned int a, b;
    asm("mov.b64 {%0, %1}, %2;" : "=r"(a), "=r"(b) : "l"(v));
    lo = __uint_as_float(a);
    hi = __uint_as_float(b);
}
__device__ __forceinline__ ull pack_dup(uint32_t h) {
    ull r;
    asm("mov.b64 %0, {%1, %1};" : "=l"(r) : "r"(h));
    return r;
}

// fast tanh: tanh(x) = 1 - 2/(exp2(2*log2e*x) + 1); abs err ~2e-7,
// saturates correctly for |x| large (exp2 -> 0 or inf).
__device__ __forceinline__ float tanh_fast(float x) {
    float e;
    asm("ex2.approx.f32 %0, %1;" : "=f"(e) : "f"(x * 2.8853900817779268f));
    float r;
    asm("rcp.approx.f32 %0, %1;" : "=f"(r) : "f"(e + 1.0f));
    return fmaf(-2.0f, r, 1.0f);
}

#define CLUSTER_ARRIVE() asm volatile("barrier.cluster.arrive.aligned;" ::: "memory")
#define CLUSTER_WAIT()   asm volatile("barrier.cluster.wait.aligned;" ::: "memory")

__device__ __forceinline__ uint32_t smem_u32(const void* p) {
    uint32_t a;
    asm("{ .reg .u64 t; cvta.to.shared.u64 t, %1; cvt.u32.u64 %0, t; }"
        : "=r"(a) : "l"(p));
    return a;
}
__device__ __forceinline__ uint32_t mapa_rank(uint32_t laddr, uint32_t rank) {
    uint32_t r;
    asm("mapa.shared::cluster.u32 %0, %1, %2;" : "=r"(r) : "r"(laddr), "r"(rank));
    return r;
}
__device__ __forceinline__ uint4 ld_cluster_v4(uint32_t addr) {
    uint4 v;
    asm volatile("ld.shared::cluster.v4.b32 {%0,%1,%2,%3}, [%4];"
                 : "=r"(v.x), "=r"(v.y), "=r"(v.z), "=r"(v.w) : "r"(addr));
    return v;
}

// ---------------------------------------------------------------------------
// Kernel 1: xW = x @ Wx + b  (unchanged — proven, rel_err 3.7e-7)
// ---------------------------------------------------------------------------
__global__ __launch_bounds__(256) void xw_gemm(
    const float* __restrict__ A,
    const float* __restrict__ B,
    const float* __restrict__ bias,
    float* __restrict__ C)
{
    __shared__ float2 As2[128][16];
    __shared__ float  Bs[16][128];

    const int m0  = blockIdx.y * 128;
    const int n0  = blockIdx.x * 128;
    const int tid = threadIdx.x;
    const int tn  = tid & 15;
    const int tm  = tid >> 4;

    ull acc[8][4];
#pragma unroll
    for (int i = 0; i < 8; i++)
#pragma unroll
        for (int j = 0; j < 4; j++) acc[i][j] = 0ULL;

    for (int k0 = 0; k0 < DI; k0 += 16) {
#pragma unroll
        for (int j = 0; j < 2; j++) {
            int f  = tid + j * 256;
            int m  = f >> 2;
            int kq = f & 3;
            float4 v = *(const float4*)(A + (size_t)(m0 + m) * DI + k0 + kq * 4);
            *(float4*)(&As2[m][kq * 4])     = make_float4(v.x, v.x, v.y, v.y);
            *(float4*)(&As2[m][kq * 4 + 2]) = make_float4(v.z, v.z, v.w, v.w);
        }
#pragma unroll
        for (int j = 0; j < 2; j++) {
            int f  = tid + j * 256;
            int k  = f >> 5;
            int nq = f & 31;
            *(float4*)(&Bs[k][nq * 4]) =
                *(const float4*)(B + (size_t)(k0 + k) * HD + n0 + nq * 4);
        }
        __syncthreads();

#pragma unroll
        for (int k = 0; k < 16; k++) {
            ulonglong2 b01 = *(const ulonglong2*)(&Bs[k][tn * 8]);
            ulonglong2 b23 = *(const ulonglong2*)(&Bs[k][tn * 8 + 4]);
#pragma unroll
            for (int i = 0; i < 8; i++) {
                ull a = *(const ull*)(&As2[tm * 8 + i][k]);
                fma2(acc[i][0], a, b01.x);
                fma2(acc[i][1], a, b01.y);
                fma2(acc[i][2], a, b23.x);
                fma2(acc[i][3], a, b23.y);
            }
        }
        __syncthreads();
    }

    const float4 bb0 = *(const float4*)(bias + n0 + tn * 8);
    const float4 bb1 = *(const float4*)(bias + n0 + tn * 8 + 4);
#pragma unroll
    for (int i = 0; i < 8; i++) {
        float r0, r1, r2, r3, r4, r5, r6, r7;
        unpack2(acc[i][0], r0, r1);
        unpack2(acc[i][1], r2, r3);
        unpack2(acc[i][2], r4, r5);
        unpack2(acc[i][3], r6, r7);
        float* p = C + (size_t)(m0 + tm * 8 + i) * HD + n0 + tn * 8;
        *(float4*)p       = make_float4(r0 + bb0.x, r1 + bb0.y, r2 + bb0.z, r3 + bb0.w);
        *(float4*)(p + 4) = make_float4(r4 + bb1.x, r5 + bb1.y, r6 + bb1.z, r7 + bb1.w);
    }
}

// ---------------------------------------------------------------------------
// Kernel 2: persistent recurrence — warp-autonomous, shuffle-reduced.
//
// Grid: 16 clusters x 8 CTAs. Cluster y: rows [8y,8y+8); CTA x: cols [64x,+64).
// Wh slice [512][64] smem-resident (oct-major, 16400B stride — proven).
//
// Hs: raw f32 h rows, stride 2192, with a 16B gap every 64 k:
//   off(k) = 4k + 16*(k>>6)  ->  the 8 intra-warp k-slices (64k apart) land
//   on 8 distinct banks for every LDS.32 (1-phase h loads).
//
// Warp w: rows {2(w&3), +1}, col half (w>>2). Lane (ksl=lane>>2, q=lane&3):
// 2 rows x 4 colpairs (cols 32(w>>2)+8q.. +8 = w-oct 4(w>>2)+q), k in
// [64ksl, 64ksl+64). Per kk: 2 LDS.32 + 2 pack + 2 LDS.128 + 8 FFMA2.
//
// Reduction: 3 shfl.bfly rounds over lane bits [2:5) (the ksl bits) with
// f32x2 adds — fully in registers, no smem, no syncthreads. Lanes ksl<2 run
// the epilogue for row row0+ksl: xw + tanh_fast + STG.128 x2 + export.
// Exchange: double-buffered raw 2KB export; ARRIVE -> prefetch next xw ->
// WAIT -> warp w pulls rank w (mapa + 4x ld.shared::cluster.v4 ->
// 4x STS.128 into the gapped Hs; rank p's k-range sits at byte 272p,
// 16B aligned). Pull skipped on final step (exit hazard). ONE syncthreads
// per step (after pull).
// ---------------------------------------------------------------------------
#define WOCT    16400
#define WS_OFF  0
#define HS_OFF  131200                    // 8*16400
#define HR      2192                      // Hs row stride
#define EXP_OFF (HS_OFF + 8 * HR)         // 148736
#define SMEM_RNN_BYTES (EXP_OFF + 2 * 2048) // 152832

__global__ __launch_bounds__(256, 1) __cluster_dims__(8, 1, 1)
void rnn_persistent(const float* __restrict__ Wh,
                    const float* __restrict__ h0,
                    float* __restrict__ out)
{
    extern __shared__ char smem[];
    const uint32_t sbase = smem_u32(smem);

    const int tid = threadIdx.x;
    const int m0  = blockIdx.y * 8;
    const int n0  = blockIdx.x * 64;

    // ---- load Wh slice once (oct-major): 8192 float4, 32/thread ----
#pragma unroll 4
    for (int j = 0; j < 32; j++) {
        int f   = tid + j * 256;
        int k   = f >> 4;
        int nq  = f & 15;
        int oct = nq >> 1;
        int hf  = nq & 1;
        *(float4*)(smem + WS_OFF + (size_t)oct * WOCT + k * 32 + hf * 16) =
            *(const float4*)(Wh + (size_t)k * HD + n0 + nq * 4);
    }
    // ---- stage h0 into gapped Hs: 1024 float4, 4/thread ----
#pragma unroll
    for (int j = 0; j < 4; j++) {
        int f   = tid + j * 256;
        int row = f >> 7;
        int q   = f & 127;                 // float4 index; k = 4q
        *(float4*)(smem + HS_OFF + row * HR + q * 16 + (q >> 4) * 16) =
            *(const float4*)(h0 + (size_t)(m0 + row) * HD + q * 4);
    }
    __syncthreads();

    const int w    = tid >> 5;
    const int lane = tid & 31;
    const int ksl  = lane >> 2;            // 0..7, k in [64ksl, 64ksl+64)
    const int q    = lane & 3;
    const int row0 = (w & 3) * 2;
    const int chal = w >> 2;
    const int colb = chal * 32 + q * 8;    // 8 cols = one w-oct
    const int oct  = chal * 4 + q;

    const char* hb = smem + HS_OFF + row0 * HR + ksl * 272;   // off(64ksl+kk)=272ksl+4kk
    const char* wb = smem + WS_OFF + (size_t)oct * WOCT + ksl * 2048;

    const bool epi  = (ksl < 2);
    const int  erow = row0 + (ksl & 1);
    float* pio = out + (size_t)(m0 + erow) * TS * HD + n0 + colb;
    float4 xa = make_float4(0.f, 0.f, 0.f, 0.f), xb = xa;
    if (epi) { xa = *(const float4*)pio; xb = *(const float4*)(pio + 4); }

    // pull mapping: warp w pulls rank w's 2KB raw export
    const int prow = lane >> 2;            // 0..7
    const int pseg = lane & 3;             // 64B segment
    char* pd = smem + HS_OFF + prow * HR + w * 272 + pseg * 64;

    for (int t = 0; t < TS; t++) {
        // ---- partial GEMM: 2 rows x 4 colpairs over 64 k ----
        ull acc[2][4];
#pragma unroll
        for (int r = 0; r < 2; r++)
#pragma unroll
            for (int j = 0; j < 4; j++) acc[r][j] = 0ULL;

#pragma unroll 16
        for (int kk = 0; kk < 64; kk++) {
            ull ha = pack_dup(*(const uint32_t*)(hb + kk * 4));
            ull hc = pack_dup(*(const uint32_t*)(hb + HR + kk * 4));
            ulonglong2 wA = *(const ulonglong2*)(wb + kk * 32);
            ulonglong2 wB = *(const ulonglong2*)(wb + kk * 32 + 16);
            fma2(acc[0][0], ha, wA.x); fma2(acc[0][1], ha, wA.y);
            fma2(acc[0][2], ha, wB.x); fma2(acc[0][3], ha, wB.y);
            fma2(acc[1][0], hc, wA.x); fma2(acc[1][1], hc, wA.y);
            fma2(acc[1][2], hc, wB.x); fma2(acc[1][3], hc, wB.y);
        }

        // ---- k-split reduction: butterfly over ksl lane bits (4,8,16) ----
#pragma unroll
        for (int m = 4; m <= 16; m <<= 1) {
#pragma unroll
            for (int r = 0; r < 2; r++)
#pragma unroll
                for (int j = 0; j < 4; j++) {
                    ull o = __shfl_xor_sync(0xffffffffu, acc[r][j], m);
                    add2(acc[r][j], o);
                }
        }

        // ---- epilogue: lanes ksl in {0,1} finalize row row0+ksl ----
        if (epi) {
            ull e0 = (ksl == 0) ? acc[0][0] : acc[1][0];
            ull e1 = (ksl == 0) ? acc[0][1] : acc[1][1];
            ull e2 = (ksl == 0) ? acc[0][2] : acc[1][2];
            ull e3 = (ksl == 0) ? acc[0][3] : acc[1][3];
            float s0, s1, s2, s3, s4, s5, s6, s7;
            unpack2(e0, s0, s1); unpack2(e1, s2, s3);
            unpack2(e2, s4, s5); unpack2(e3, s6, s7);
            float4 o0, o1;
            o0.x = tanh_fast(xa.x + s0);
            o0.y = tanh_fast(xa.y + s1);
            o0.z = tanh_fast(xa.z + s2);
            o0.w = tanh_fast(xa.w + s3);
            o1.x = tanh_fast(xb.x + s4);
            o1.y = tanh_fast(xb.y + s5);
            o1.z = tanh_fast(xb.z + s6);
            o1.w = tanh_fast(xb.w + s7);

            // output (never re-read: no fence needed)
            *(float4*)pio       = o0;
            *(float4*)(pio + 4) = o1;

            // raw export (double-buffered, 2KB = 8 rows x 256B)
            char* eb = smem + EXP_OFF + (t & 1) * 2048 + erow * 256 + colb * 4;
            *(float4*)eb        = o0;
            *(float4*)(eb + 16) = o1;
        }

        // ---- exchange barrier: arrive, prefetch next xw, wait ----
        CLUSTER_ARRIVE();
        pio += HD;
        if (epi && t < TS - 1) {
            xa = *(const float4*)pio;
            xb = *(const float4*)(pio + 4);
        }
        CLUSTER_WAIT();

        // ---- pull all 8 ranks' raw exports into gapped Hs ----
        // Skipped on final step: no peer-SMEM access after the last barrier.
        if (t < TS - 1) {
            uint32_t src = mapa_rank(
                sbase + EXP_OFF + (t & 1) * 2048 + prow * 256 + pseg * 64, w);
            uint4 v0 = ld_cluster_v4(src);
            uint4 v1 = ld_cluster_v4(src + 16);
            uint4 v2 = ld_cluster_v4(src + 32);
            uint4 v3 = ld_cluster_v4(src + 48);
            *(uint4*)(pd)      = v0;
            *(uint4*)(pd + 16) = v1;
            *(uint4*)(pd + 32) = v2;
            *(uint4*)(pd + 48) = v3;
        }
        __syncthreads();
    }
}

// ---------------------------------------------------------------------------
// Launch
// ---------------------------------------------------------------------------
extern "C" void kernel_launch(void* const* d_in, const int* in_sizes, int n_in,
                              void* d_out, int out_size) {
    (void)in_sizes; (void)n_in; (void)out_size;
    const float* x  = (const float*)d_in[0];   // [128, 512, 512]
    const float* h0 = (const float*)d_in[1];   // [128, 512]
    const float* Wx = (const float*)d_in[2];   // [512, 512]
    const float* Wh = (const float*)d_in[3];   // [512, 512]
    const float* b  = (const float*)d_in[4];   // [512]
    float* out = (float*)d_out;                // [128, 512, 512]

    dim3 gx(HD / 128, (NB * TS) / 128);        // (4, 512)
    xw_gemm<<<gx, 256>>>(x, Wx, b, out);

    cudaFuncSetAttribute(rnn_persistent,
                         cudaFuncAttributeMaxDynamicSharedMemorySize,
                         SMEM_RNN_BYTES);
    dim3 gs(8, NB / 8);                        // 8 CTAs/cluster x 16 clusters
    rnn_persistent<<<gs, 256, SMEM_RNN_BYTES>>>(Wh, h0, out);
}

// round 16
// speedup vs baseline: 1.6138x; 1.6138x over previous
#include <cuda_runtime.h>
#include <math.h>
#include <stdint.h>

// Problem constants
#define NB 128   // batch
#define TS 512   // timesteps
#define DI 512   // input dim
#define HD 512   // hidden dim

typedef unsigned long long ull;

// ---------------- packed f32x2 helpers (sm_100+ FFMA2 path) ----------------
__device__ __forceinline__ void fma2(ull& acc, ull a, ull b) {
    asm("fma.rn.f32x2 %0, %1, %2, %0;" : "+l"(acc) : "l"(a), "l"(b));
}
__device__ __forceinline__ void add2(ull& a, ull b) {
    asm("add.rn.f32x2 %0, %0, %1;" : "+l"(a) : "l"(b));
}
__device__ __forceinline__ void unpack2(ull v, float& lo, float& hi) {
    unsigned int a, b;
    asm("mov.b64 {%0, %1}, %2;" : "=r"(a), "=r"(b) : "l"(v));
    lo = __uint_as_float(a);
    hi = __uint_as_float(b);
}
__device__ __forceinline__ ull pack_dup(uint32_t h) {
    ull r;
    asm("mov.b64 %0, {%1, %1};" : "=l"(r) : "r"(h));
    return r;
}

__device__ __forceinline__ uint32_t smem_u32(const void* p) {
    uint32_t a;
    asm("{ .reg .u64 t; cvta.to.shared.u64 t, %1; cvt.u32.u64 %0, t; }"
        : "=r"(a) : "l"(p));
    return a;
}

// ---------------- cp.async + mbarrier ----------------
__device__ __forceinline__ void cp_async16(uint32_t dst, const void* src) {
    asm volatile("cp.async.cg.shared.global [%0], [%1], 16;"
                 :: "r"(dst), "l"(src) : "memory");
}
__device__ __forceinline__ void cp_async_arrive(uint32_t mbar) {
    asm volatile("cp.async.mbarrier.arrive.noinc.shared.b64 [%0];"
                 :: "r"(mbar) : "memory");
}
__device__ __forceinline__ void mbar_init(uint32_t mbar, uint32_t cnt) {
    asm volatile("mbarrier.init.shared.b64 [%0], %1;"
                 :: "r"(mbar), "r"(cnt) : "memory");
}
__device__ __forceinline__ void mbar_wait0(uint32_t mbar) {
    asm volatile(
        "{\n\t.reg .pred P;\n\t"
        "W%=:\n\t"
        "mbarrier.try_wait.parity.shared.b64 P, [%0], 0;\n\t"
        "@!P bra W%=;\n\t}"
        :: "r"(mbar) : "memory");
}

// ---------------- PDL (programmatic dependent launch) ----------------
__device__ __forceinline__ void pdl_wait() {
    asm volatile("griddepcontrol.wait;" ::: "memory");
}
__device__ __forceinline__ void pdl_trigger() {
    asm volatile("griddepcontrol.launch_dependents;" ::: "memory");
}

// ---------------------------------------------------------------------------
// Kernel 1: xW = x @ Wx + b  (unchanged — proven, rel_err 3.7e-7)
// ---------------------------------------------------------------------------
__global__ __launch_bounds__(256) void xw_gemm(
    const float* __restrict__ A,
    const float* __restrict__ B,
    const float* __restrict__ bias,
    float* __restrict__ C)
{
    __shared__ float2 As2[128][16];
    __shared__ float  Bs[16][128];

    const int m0  = blockIdx.y * 128;
    const int n0  = blockIdx.x * 128;
    const int tid = threadIdx.x;
    const int tn  = tid & 15;
    const int tm  = tid >> 4;

    ull acc[8][4];
#pragma unroll
    for (int i = 0; i < 8; i++)
#pragma unroll
        for (int j = 0; j < 4; j++) acc[i][j] = 0ULL;

    for (int k0 = 0; k0 < DI; k0 += 16) {
#pragma unroll
        for (int j = 0; j < 2; j++) {
            int f  = tid + j * 256;
            int m  = f >> 2;
            int kq = f & 3;
            float4 v = *(const float4*)(A + (size_t)(m0 + m) * DI + k0 + kq * 4);
            *(float4*)(&As2[m][kq * 4])     = make_float4(v.x, v.x, v.y, v.y);
            *(float4*)(&As2[m][kq * 4 + 2]) = make_float4(v.z, v.z, v.w, v.w);
        }
#pragma unroll
        for (int j = 0; j < 2; j++) {
            int f  = tid + j * 256;
            int k  = f >> 5;
            int nq = f & 31;
            *(float4*)(&Bs[k][nq * 4]) =
                *(const float4*)(B + (size_t)(k0 + k) * HD + n0 + nq * 4);
        }
        __syncthreads();

#pragma unroll
        for (int k = 0; k < 16; k++) {
            ulonglong2 b01 = *(const ulonglong2*)(&Bs[k][tn * 8]);
            ulonglong2 b23 = *(const ulonglong2*)(&Bs[k][tn * 8 + 4]);
#pragma unroll
            for (int i = 0; i < 8; i++) {
                ull a = *(const ull*)(&As2[tm * 8 + i][k]);
                fma2(acc[i][0], a, b01.x);
                fma2(acc[i][1], a, b01.y);
                fma2(acc[i][2], a, b23.x);
                fma2(acc[i][3], a, b23.y);
            }
        }
        __syncthreads();
    }

    const float4 bb0 = *(const float4*)(bias + n0 + tn * 8);
    const float4 bb1 = *(const float4*)(bias + n0 + tn * 8 + 4);
#pragma unroll
    for (int i = 0; i < 8; i++) {
        float r0, r1, r2, r3, r4, r5, r6, r7;
        unpack2(acc[i][0], r0, r1);
        unpack2(acc[i][1], r2, r3);
        unpack2(acc[i][2], r4, r5);
        unpack2(acc[i][3], r6, r7);
        float* p = C + (size_t)(m0 + tm * 8 + i) * HD + n0 + tn * 8;
        *(float4*)p       = make_float4(r0 + bb0.x, r1 + bb0.y, r2 + bb0.z, r3 + bb0.w);
        *(float4*)(p + 4) = make_float4(r4 + bb1.x, r5 + bb1.y, r6 + bb1.z, r7 + bb1.w);
    }
}

// ---------------------------------------------------------------------------
// Kernel 2: ONE recurrence step (per-step launch, PDL-overlapped).
//
// Grid (8,16): CTA = 8 rows x 64 cols of h_t. 256 threads.
// R12's proven compute core:
//   Ws oct-major (WOCT=16400B stride) — LDS.128 4-phase clean.
//   Hs k-swizzled (off(k)=4k+16(k>>4), HR=2576) — LDS.32 1-phase.
//   Thread (ksl=tid>>3, grp=tid&7): 8 rows x 8 cols over k in [16ksl,+16).
//   Partial dump -> smem tree reduce -> xw + tanhf -> STG.
//
// Step-boundary overlap:
//   - Wh slice streamed via cp.async in 4 chunks (mbarrier each), ISSUED
//     BEFORE griddepcontrol.wait — runs during the previous step's tail.
//   - griddepcontrol.launch_dependents after the output stores lets the
//     next step launch + run its Wh prologue while this one drains.
//   - Warp w waits only its own chunk (w>>1): chunks 0..3 consumed in order.
// ---------------------------------------------------------------------------
#define WOCT    16400
#define WS_OFF  0
#define HS_OFF  131200                    // 8 oct regions
#define HR      2576
#define RED_OFF (HS_OFF + 8 * HR)         // 151808
#define MB_OFF  (RED_OFF + 256 * 272)     // 221440
#define STEP_SMEM (MB_OFF + 64)           // 221504

__global__ __launch_bounds__(256, 1)
void rnn_step(const float* __restrict__ Wh,
              const float* __restrict__ hsrc, int hstride,
              float* __restrict__ io /* out + t*HD */)
{
    extern __shared__ char smem[];
    const uint32_t sb = smem_u32(smem);
    const int tid = threadIdx.x;
    const int m0  = blockIdx.y * 8;
    const int n0  = blockIdx.x * 64;

    // mbarriers for the 4 Wh chunks (fresh each launch -> parity 0)
    if (tid == 0) {
#pragma unroll
        for (int c = 0; c < 4; c++) mbar_init(sb + MB_OFF + 8 * c, 256);
    }
    __syncthreads();

    // ---- stream Wh slice (const input): 4 chunks x 8 float4 per thread ----
    // Issued BEFORE the dependency wait: overlaps the previous step kernel.
#pragma unroll
    for (int c = 0; c < 4; c++) {
#pragma unroll
        for (int j = 0; j < 8; j++) {
            int f   = tid + (c * 8 + j) * 256;
            int k   = f >> 4;
            int nq  = f & 15;
            int oct = nq >> 1;
            int hf  = nq & 1;
            cp_async16(sb + WS_OFF + oct * WOCT + k * 32 + hf * 16,
                       Wh + (size_t)k * HD + n0 + nq * 4);
        }
        cp_async_arrive(sb + MB_OFF + 8 * c);
    }

    // ---- wait for previous step's h (and xw_gemm's xw) to be visible ----
    pdl_wait();

    // ---- load h tile into swizzled Hs: 1024 float4, 4/thread ----
#pragma unroll
    for (int j = 0; j < 4; j++) {
        int f   = tid + j * 256;
        int row = f >> 7;
        int q   = f & 127;            // float4 index; k = 4q
        *(float4*)(smem + HS_OFF + row * HR + q * 16 + (q >> 2) * 16) =
            *(const float4*)(hsrc + (size_t)(m0 + row) * hstride + q * 4);
    }

    // xw prefetch for this thread's output slot
    const int er  = tid >> 5;
    const int ecp = tid & 31;
    float* pio = io + (size_t)(m0 + er) * (TS * HD) + n0 + ecp * 2;
    float2 xw = *(const float2*)pio;
    __syncthreads();

    // ---- wait for this warp's Wh chunk (warp-uniform: chunk = warp>>1) ----
    const int ksl = tid >> 3;          // 0..31, k in [16ksl, 16ksl+16)
    const int grp = tid & 7;           // col oct
    mbar_wait0(sb + MB_OFF + 8 * (ksl >> 3));

    const char* hb = smem + HS_OFF + ksl * 80;                 // + r*HR + kk*4
    const char* wb = smem + WS_OFF + (size_t)grp * WOCT + ksl * 512;

    // ---- 8x8 register-blocked partial GEMM over 16 k (R12 core) ----
    ull acc[8][4];
#pragma unroll
    for (int r = 0; r < 8; r++)
#pragma unroll
        for (int j = 0; j < 4; j++) acc[r][j] = 0ULL;

#pragma unroll 8
    for (int kk = 0; kk < 16; kk++) {
        ull hp[8];
#pragma unroll
        for (int r = 0; r < 8; r++)
            hp[r] = pack_dup(*(const uint32_t*)(hb + r * HR + kk * 4));
        ulonglong2 wA = *(const ulonglong2*)(wb + kk * 32);
        ulonglong2 wB = *(const ulonglong2*)(wb + kk * 32 + 16);
#pragma unroll
        for (int r = 0; r < 8; r++) {
            fma2(acc[r][0], hp[r], wA.x);
            fma2(acc[r][1], hp[r], wA.y);
            fma2(acc[r][2], hp[r], wB.x);
            fma2(acc[r][3], hp[r], wB.y);
        }
    }

    // ---- dump 32 partials (R12 layout: slot*272 + ksl*8) ----
    char* pstore = smem + RED_OFF + (grp * 4) * 272 + ksl * 8;
#pragma unroll
    for (int r = 0; r < 8; r++)
#pragma unroll
        for (int j = 0; j < 4; j++)
            *(ull*)(pstore + (size_t)r * 32 * 272 + j * 272) = acc[r][j];
    __syncthreads();

    // ---- tree reduce 32 partials of slot tid + epilogue ----
    {
        const char* rb = smem + RED_OFF + tid * 272;
        ulonglong2 v[16];
#pragma unroll
        for (int q = 0; q < 16; q++)
            v[q] = *(const ulonglong2*)(rb + q * 16);
        ull s[8];
#pragma unroll
        for (int q = 0; q < 8; q++) {
            ull a = v[2 * q].x;
            add2(a, v[2 * q].y);
            ull b = v[2 * q + 1].x;
            add2(b, v[2 * q + 1].y);
            add2(a, b);
            s[q] = a;
        }
        add2(s[0], s[1]); add2(s[2], s[3]); add2(s[4], s[5]); add2(s[6], s[7]);
        add2(s[0], s[2]); add2(s[4], s[6]);
        add2(s[0], s[4]);

        float slo, shi;
        unpack2(s[0], slo, shi);
        float2 hv;
        hv.x = tanhf(xw.x + slo);
        hv.y = tanhf(xw.y + shi);
        *(float2*)pio = hv;
    }

    // ---- let the next step launch + start its Wh prologue ----
    pdl_trigger();
}

// ---------------------------------------------------------------------------
// Launch: xW into d_out, then 512 PDL-chained step kernels.
// ---------------------------------------------------------------------------
extern "C" void kernel_launch(void* const* d_in, const int* in_sizes, int n_in,
                              void* d_out, int out_size) {
    (void)in_sizes; (void)n_in; (void)out_size;
    const float* x  = (const float*)d_in[0];   // [128, 512, 512]
    const float* h0 = (const float*)d_in[1];   // [128, 512]
    const float* Wx = (const float*)d_in[2];   // [512, 512]
    const float* Wh = (const float*)d_in[3];   // [512, 512]
    const float* b  = (const float*)d_in[4];   // [512]
    float* out = (float*)d_out;                // [128, 512, 512]

    dim3 gx(HD / 128, (NB * TS) / 128);        // (4, 512)
    xw_gemm<<<gx, 256>>>(x, Wx, b, out);

    cudaFuncSetAttribute(rnn_step,
                         cudaFuncAttributeMaxDynamicSharedMemorySize,
                         STEP_SMEM);

    cudaLaunchAttribute at[1];
    at[0].id = cudaLaunchAttributeProgrammaticStreamSerialization;
    at[0].val.programmaticStreamSerializationAllowed = 1;

    for (int t = 0; t < TS; t++) {
        const float* hs = (t == 0) ? h0 : (out + (size_t)(t - 1) * HD);
        int hstride = (t == 0) ? HD : TS * HD;
        float* io = out + (size_t)t * HD;

        cudaLaunchConfig_t cfg = {};
        cfg.gridDim         = dim3(8, 16, 1);
        cfg.blockDim        = dim3(256, 1, 1);
        cfg.dynamicSmemBytes = STEP_SMEM;
        cfg.stream          = 0;
        cfg.attrs           = at;
        cfg.numAttrs        = 1;

        cudaError_t e = cudaLaunchKernelEx(&cfg, rnn_step, Wh, hs, hstride, io);
        if (e != cudaSuccess) {
            // PDL attr rejected: plain launch (griddepcontrol ops are no-ops)
            rnn_step<<<dim3(8, 16), 256, STEP_SMEM>>>(Wh, hs, hstride, io);
        }
    }
}